// round 9
// baseline (speedup 1.0000x reference)
#include <cuda_runtime.h>
#include <math.h>

#define BB 4
#define NN 4096
#define DD 8
#define KK 64               /* instance ids */
#define CC1 16              /* pass1 chunks per batch */
#define CH1 256             /* pass1 threads */
#define JTILE 32            /* j per rep tile (16 packed pairs) */
#define ITILE 256           /* i per rep tile (2 per thread) */
#define RATIO (ITILE / JTILE)   /* 8 */
#define NTI_MAX (NN / ITILE)    /* 16 */
#define NTJ_MAX (NN / JTILE)    /* 128 */
#define TA   128            /* attraction tasks: 4 batches x 32 chunks of 128 */
#define G2   1280           /* K2 grid size */
#define T2   128            /* K2 threads */

#define LOG2E  1.4426950408889634f
#define SCALE  1.6986436f   /* sqrt(2*log2(e)) */

typedef unsigned long long ull;

// ---------------- scratch (no allocations; zero-init valid) ----------------
__device__ float g_cp_emb[BB][NN][DD];   // compacted CP embeddings, pre-scaled by SCALE
__device__ float g_nsq   [BB][NN];       // -|e_raw|^2 * log2(e)
__device__ int   g_pos     [BB];
__device__ int   g_cnt     [BB][KK];
__device__ int   g_firstmax[BB][KK];     // max(NN - i); 0 = no CP
__device__ float g_bce1    [BB];
__device__ float g_bce0    [BB];
__device__ float g_seg     [BB][KK];
__device__ float g_repsum  [BB];
__device__ int   g_done;

__device__ __forceinline__ float ex2f(float x) {
    float r; asm("ex2.approx.ftz.f32 %0, %1;" : "=f"(r) : "f"(x)); return r;
}
__device__ __forceinline__ float softplus_f(float x) {
    return fmaxf(x, 0.f) + log1pf(expf(-fabsf(x)));
}
__device__ __forceinline__ ull ffma2(ull a, ull b, ull c) {
    ull d; asm("fma.rn.f32x2 %0, %1, %2, %3;" : "=l"(d) : "l"(a), "l"(b), "l"(c));
    return d;
}
__device__ __forceinline__ ull addx2(ull a, ull b) {
    ull d; asm("add.rn.f32x2 %0, %1, %2;" : "=l"(d) : "l"(a), "l"(b));
    return d;
}
__device__ __forceinline__ ull packx2(float lo, float hi) {
    ull d; asm("mov.b64 %0, {%1, %2};" : "=l"(d) : "f"(lo), "f"(hi));
    return d;
}
__device__ __forceinline__ void unpackx2(float& lo, float& hi, ull v) {
    asm("mov.b64 {%0, %1}, %2;" : "=f"(lo), "=f"(hi) : "l"(v));
}

// ============ kernel 1: counts, first-CP, BCE, scaled CP compaction ============
__global__ void __launch_bounds__(CH1) k_pass1(const float* __restrict__ beta,
                                               const float* __restrict__ embed,
                                               const int*   __restrict__ sid,
                                               const int*   __restrict__ iscp)
{
    const int c   = blockIdx.x;
    const int b   = blockIdx.y;
    const int tid = threadIdx.x;
    const int i   = c * CH1 + tid;
    const int g   = b * NN + i;
    const int lane = tid & 31;

    __shared__ int   s_cnt[KK];
    __shared__ int   s_first[KK];
    __shared__ float s_w1[CH1 / 32];
    __shared__ float s_w0[CH1 / 32];

    if (tid < KK) { s_cnt[tid] = 0; s_first[tid] = NN; }
    __syncthreads();

    const int   s  = sid[g];
    const int   cp = iscp[g];
    const float bt = beta[g];

    atomicAdd(&s_cnt[s], 1);
    float l1 = 0.f, l0 = 0.f;
    if (cp == 1) { atomicMin(&s_first[s], i); l1 = softplus_f(-bt); }
    else         { l0 = softplus_f(bt); }

    const unsigned bal = __ballot_sync(0xffffffffu, cp == 1);
    if (bal) {
        const int nw = __popc(bal);
        const int leader = __ffs(bal) - 1;
        int base = 0;
        if (lane == leader) base = atomicAdd(&g_pos[b], nw);
        base = __shfl_sync(0xffffffffu, base, leader);
        if (cp == 1) {
            const int w = base + __popc(bal & ((1u << lane) - 1u));
            const float4* e = (const float4*)&embed[(size_t)g * DD];
            float4 a = e[0], d = e[1];
            float sq = a.x*a.x + a.y*a.y + a.z*a.z + a.w*a.w
                     + d.x*d.x + d.y*d.y + d.z*d.z + d.w*d.w;
            *(float4*)&g_cp_emb[b][w][0] = make_float4(a.x*SCALE, a.y*SCALE, a.z*SCALE, a.w*SCALE);
            *(float4*)&g_cp_emb[b][w][4] = make_float4(d.x*SCALE, d.y*SCALE, d.z*SCALE, d.w*SCALE);
            g_nsq[b][w] = -sq * LOG2E;
        }
    }

    #pragma unroll
    for (int off = 16; off; off >>= 1) {
        l1 += __shfl_down_sync(0xffffffffu, l1, off);
        l0 += __shfl_down_sync(0xffffffffu, l0, off);
    }
    if (lane == 0) { s_w1[tid >> 5] = l1; s_w0[tid >> 5] = l0; }
    __syncthreads();

    if (tid < KK) {
        if (s_cnt[tid] > 0)    atomicAdd(&g_cnt[b][tid], s_cnt[tid]);
        if (s_first[tid] < NN) atomicMax(&g_firstmax[b][tid], NN - s_first[tid]);
    }
    if (tid == 0) {
        float S1 = 0.f, S0 = 0.f;
        #pragma unroll
        for (int w = 0; w < CH1 / 32; w++) { S1 += s_w1[w]; S0 += s_w0[w]; }
        atomicAdd(&g_bce1[b], S1);
        atomicAdd(&g_bce0[b], S0);
    }
}

// ============ kernel 2: task-queued attraction + repulsion + elected finalize ============
__global__ void __launch_bounds__(T2) k_main(const float* __restrict__ embed,
                                             const int*   __restrict__ sid,
                                             float* __restrict__ out)
{
    const int t    = threadIdx.x;
    const int lane = t & 31;

    __shared__ __align__(16) ull sJ[JTILE/2][10];   // packed j-pair rows (80B each)
    __shared__ float sred[8];
    __shared__ float s_cpe[KK][DD];
    __shared__ int   s_f[KK];
    __shared__ float s_seg[KK];
    __shared__ int   s_P[BB];
    __shared__ int   s_last;

    if (t < BB) s_P[t] = g_pos[t];
    __syncthreads();

    // total task count (uniform)
    int total = TA;
    #pragma unroll
    for (int bb = 0; bb < BB; bb++) {
        int P   = s_P[bb];
        int nti = min(NTI_MAX, (P + ITILE - 1) >> 8);
        int ntj = min(NTJ_MAX, (P + JTILE - 1) >> 5);
        total += nti * ntj - (RATIO / 2) * nti * (nti - 1);  // sum_{ti<nti}(ntj - RATIO*ti)
    }

    for (int task = blockIdx.x; task < total; task += G2) {
        __syncthreads();                            // protect smem reuse across tasks
        if (task < TA) {
            // ---------------- attraction chunk ----------------
            const int b = task >> 5;
            const int c = task & 31;
            if (t < KK) {
                int m = g_firstmax[b][t];
                s_f[t]   = m;
                s_seg[t] = 0.f;
                if (m > 0) {
                    int f = NN - m;
                    const float4* e = (const float4*)&embed[((size_t)b * NN + f) * DD];
                    *(float4*)&s_cpe[t][0] = e[0];
                    *(float4*)&s_cpe[t][4] = e[1];
                }
            }
            __syncthreads();

            const int g = b * NN + c * T2 + t;
            const int s = sid[g];
            if (s_f[s] > 0) {
                const float4* e = (const float4*)&embed[(size_t)g * DD];
                float4 a = e[0], d = e[1];
                float x0 = a.x - s_cpe[s][0], x1 = a.y - s_cpe[s][1];
                float x2 = a.z - s_cpe[s][2], x3 = a.w - s_cpe[s][3];
                float x4 = d.x - s_cpe[s][4], x5 = d.y - s_cpe[s][5];
                float x6 = d.z - s_cpe[s][6], x7 = d.w - s_cpe[s][7];
                float d2 = x0*x0 + x1*x1 + x2*x2 + x3*x3 + x4*x4 + x5*x5 + x6*x6 + x7*x7;
                atomicAdd(&s_seg[s], d2);
            }
            __syncthreads();
            if (t < KK && s_seg[t] != 0.f) atomicAdd(&g_seg[b][t], s_seg[t]);
        } else {
            // ---------------- repulsion tile (256 i x 32 j) ----------------
            int q = task - TA;
            int b = 0, ntj = 0;
            #pragma unroll
            for (int bb = 0; bb < BB; bb++) {
                int P   = s_P[bb];
                int ti_ = min(NTI_MAX, (P + ITILE - 1) >> 8);
                int tj_ = min(NTJ_MAX, (P + JTILE - 1) >> 5);
                int tri = ti_ * tj_ - (RATIO / 2) * ti_ * (ti_ - 1);
                if (bb < BB - 1 && q >= tri) { q -= tri; b = bb + 1; }
                else if (bb == b) { ntj = tj_; }
            }
            int ti = 0, rem = ntj;
            while (q >= rem) { q -= rem; ti++; rem -= RATIO; }
            const int tj = RATIO * ti + q;

            const int P  = s_P[b];
            const int i0 = ti * ITILE;
            const int j0 = tj * JTILE;
            const int jn = min(JTILE, P - j0);

            // pack 16 j-pair rows into smem (from row-major global)
            if (t < JTILE / 2) {
                const int j0g = j0 + 2 * t;
                const int j1g = j0g + 1;
                float4 a0 = *(const float4*)&g_cp_emb[b][j0g][0];
                float4 a1 = *(const float4*)&g_cp_emb[b][j0g][4];
                float4 b0 = *(const float4*)&g_cp_emb[b][j1g][0];
                float4 b1 = *(const float4*)&g_cp_emb[b][j1g][4];
                float n0 = g_nsq[b][j0g], n1 = g_nsq[b][j1g];
                ull* row = sJ[t];
                row[0] = packx2(a0.x, b0.x); row[1] = packx2(a0.y, b0.y);
                row[2] = packx2(a0.z, b0.z); row[3] = packx2(a0.w, b0.w);
                row[4] = packx2(a1.x, b1.x); row[5] = packx2(a1.y, b1.y);
                row[6] = packx2(a1.z, b1.z); row[7] = packx2(a1.w, b1.w);
                row[8] = packx2(n0, n1);
            }

            // i-side: 2 rows per thread, broadcast-packed
            const int gi0 = i0 + t;
            const int gi1 = gi0 + 128;
            float4 ea0 = *(const float4*)&g_cp_emb[b][gi0][0];
            float4 eb0 = *(const float4*)&g_cp_emb[b][gi0][4];
            float4 ea1 = *(const float4*)&g_cp_emb[b][gi1][0];
            float4 eb1 = *(const float4*)&g_cp_emb[b][gi1][4];
            ull a0_0 = packx2(ea0.x, ea0.x), a0_1 = packx2(ea0.y, ea0.y);
            ull a0_2 = packx2(ea0.z, ea0.z), a0_3 = packx2(ea0.w, ea0.w);
            ull a0_4 = packx2(eb0.x, eb0.x), a0_5 = packx2(eb0.y, eb0.y);
            ull a0_6 = packx2(eb0.z, eb0.z), a0_7 = packx2(eb0.w, eb0.w);
            ull a1_0 = packx2(ea1.x, ea1.x), a1_1 = packx2(ea1.y, ea1.y);
            ull a1_2 = packx2(ea1.z, ea1.z), a1_3 = packx2(ea1.w, ea1.w);
            ull a1_4 = packx2(eb1.x, eb1.x), a1_5 = packx2(eb1.y, eb1.y);
            ull a1_6 = packx2(eb1.z, eb1.z), a1_7 = packx2(eb1.w, eb1.w);
            float nqs0 = (gi0 < P) ? g_nsq[b][gi0] : -3.0e38f;   // invalid -> ex2 underflow
            float nqs1 = (gi1 < P) ? g_nsq[b][gi1] : -3.0e38f;
            ull nq2_0 = packx2(nqs0, nqs0);
            ull nq2_1 = packx2(nqs1, nqs1);
            __syncthreads();

            float accA = 0.f, accB = 0.f, accC = 0.f, accD = 0.f;
            const bool clean = (tj >= RATIO * ti + RATIO) && (jn == JTILE);
            if (clean) {
                #pragma unroll 4
                for (int jj = 0; jj < JTILE / 2; jj++) {
                    const ull* row = sJ[jj];
                    ulonglong2 r01 = *(const ulonglong2*)&row[0];
                    ulonglong2 r23 = *(const ulonglong2*)&row[2];
                    ulonglong2 r45 = *(const ulonglong2*)&row[4];
                    ulonglong2 r67 = *(const ulonglong2*)&row[6];
                    ull seed = row[8];
                    ull ca = ffma2(a0_0, r01.x, seed);
                    ca = ffma2(a0_1, r01.y, ca);
                    ca = ffma2(a0_2, r23.x, ca);
                    ca = ffma2(a0_3, r23.y, ca);
                    ull cb = ffma2(a0_4, r45.x, nq2_0);
                    cb = ffma2(a0_5, r45.y, cb);
                    cb = ffma2(a0_6, r67.x, cb);
                    cb = ffma2(a0_7, r67.y, cb);
                    float lo, hi;
                    unpackx2(lo, hi, addx2(ca, cb));
                    accA += ex2f(lo);
                    accB += ex2f(hi);
                    ull da = ffma2(a1_0, r01.x, seed);
                    da = ffma2(a1_1, r01.y, da);
                    da = ffma2(a1_2, r23.x, da);
                    da = ffma2(a1_3, r23.y, da);
                    ull db = ffma2(a1_4, r45.x, nq2_1);
                    db = ffma2(a1_5, r45.y, db);
                    db = ffma2(a1_6, r67.x, db);
                    db = ffma2(a1_7, r67.y, db);
                    unpackx2(lo, hi, addx2(da, db));
                    accC += ex2f(lo);
                    accD += ex2f(hi);
                }
            } else {
                const int jn2 = (jn + 1) >> 1;
                for (int jj = 0; jj < jn2; jj++) {
                    const ull* row = sJ[jj];
                    ulonglong2 r01 = *(const ulonglong2*)&row[0];
                    ulonglong2 r23 = *(const ulonglong2*)&row[2];
                    ulonglong2 r45 = *(const ulonglong2*)&row[4];
                    ulonglong2 r67 = *(const ulonglong2*)&row[6];
                    ull seed = row[8];
                    const int jg0 = j0 + 2 * jj;
                    const int jg1 = jg0 + 1;
                    ull ca = ffma2(a0_0, r01.x, seed);
                    ca = ffma2(a0_1, r01.y, ca);
                    ca = ffma2(a0_2, r23.x, ca);
                    ca = ffma2(a0_3, r23.y, ca);
                    ull cb = ffma2(a0_4, r45.x, nq2_0);
                    cb = ffma2(a0_5, r45.y, cb);
                    cb = ffma2(a0_6, r67.x, cb);
                    cb = ffma2(a0_7, r67.y, cb);
                    float lo, hi;
                    unpackx2(lo, hi, addx2(ca, cb));
                    accA += (jg0 > gi0 && jg0 < P) ? ex2f(lo) : 0.f;
                    accB += (jg1 > gi0 && jg1 < P) ? ex2f(hi) : 0.f;
                    ull da = ffma2(a1_0, r01.x, seed);
                    da = ffma2(a1_1, r01.y, da);
                    da = ffma2(a1_2, r23.x, da);
                    da = ffma2(a1_3, r23.y, da);
                    ull db = ffma2(a1_4, r45.x, nq2_1);
                    db = ffma2(a1_5, r45.y, db);
                    db = ffma2(a1_6, r67.x, db);
                    db = ffma2(a1_7, r67.y, db);
                    unpackx2(lo, hi, addx2(da, db));
                    accC += (jg0 > gi1 && jg0 < P) ? ex2f(lo) : 0.f;
                    accD += (jg1 > gi1 && jg1 < P) ? ex2f(hi) : 0.f;
                }
            }

            float acc = (accA + accB) + (accC + accD);
            #pragma unroll
            for (int off = 16; off; off >>= 1)
                acc += __shfl_down_sync(0xffffffffu, acc, off);
            if (lane == 0) atomicAdd(&g_repsum[b], acc);
        }
    }

    // ---------------- global election ----------------
    __threadfence();
    __syncthreads();
    if (t == 0) {
        int old = atomicAdd(&g_done, 1);
        s_last = (old == G2 - 1);
    }
    __syncthreads();
    if (!s_last) return;
    __threadfence();

    // ======== finalize (one block; warp w handles batch w) ========
    {
        const int b = t >> 5;
        float attr = 0.f;
        #pragma unroll
        for (int qq = 0; qq < KK / 32; qq++) {
            int k = lane + qq * 32;
            int m   = g_firstmax[b][k];
            int cnt = g_cnt[b][k];
            float seg = g_seg[b][k];
            attr += (m > 0 && cnt > 0) ? seg / fmaxf((float)cnt, 1.f) : 0.f;
        }
        #pragma unroll
        for (int off = 16; off; off >>= 1)
            attr += __shfl_down_sync(0xffffffffu, attr, off);
        if (lane == 0) {
            float pos = (float)s_P[b];
            float neg = (float)NN - pos;
            int   valid = (pos >= 1.f) && (neg >= 1.f);
            float pw  = neg / (pos + 1e-6f);
            float bce = (pw * g_bce1[b] + g_bce0[b]) / (float)NN;
            float S   = g_repsum[b];
            float rep_sum = pos + 2.f * S;                 // diagonal = pos exactly
            float rep = (pos > 1.f) ? rep_sum / fmaxf(pos * pos, 1.f) : 0.f;
            sred[b]     = valid ? (bce + attr + rep) : 0.f;
            sred[4 + b] = valid ? 1.f : 0.f;
        }
    }
    __syncthreads();
    if (t == 0) {
        float ts = 0.f, cnt = 0.f;
        #pragma unroll
        for (int bb = 0; bb < BB; bb++) { ts += sred[bb]; cnt += sred[4 + bb]; }
        out[0] = (cnt > 0.f) ? ts / fmaxf(cnt, 1.f) : 0.f;
    }
    __syncthreads();
    // reset accumulators for the next graph replay
    for (int idx = t; idx < BB * KK; idx += T2) {
        int bb = idx >> 6, k = idx & 63;
        g_cnt[bb][k]      = 0;
        g_firstmax[bb][k] = 0;
        g_seg[bb][k]      = 0.f;
    }
    if (t < BB) {
        g_pos[t]    = 0;
        g_repsum[t] = 0.f;
        g_bce1[t]   = 0.f;
        g_bce0[t]   = 0.f;
    }
    if (t == 0) g_done = 0;
}

// ================= launch =================
extern "C" void kernel_launch(void* const* d_in, const int* in_sizes, int n_in,
                              void* d_out, int out_size)
{
    const float* beta  = (const float*)d_in[0];
    const float* embed = (const float*)d_in[1];
    const int*   sid   = (const int*)  d_in[2];
    const int*   iscp  = (const int*)  d_in[3];
    float* out = (float*)d_out;

    dim3 g1(CC1, BB);
    k_pass1<<<g1, CH1>>>(beta, embed, sid, iscp);
    k_main<<<G2, T2>>>(embed, sid, out);
}

// round 10
// speedup vs baseline: 1.2315x; 1.2315x over previous
#include <cuda_runtime.h>
#include <math.h>

#define BB 4
#define NN 4096
#define DD 8
#define KK 64               /* instance ids */
#define CC1 16              /* pass1 chunks per batch */
#define CH1 256             /* pass1 threads */
#define JTILE 64            /* j per rep tile (32 packed pairs) */
#define ITILE 256           /* i per rep tile (2 per thread) */
#define RATIO (ITILE / JTILE)   /* 4 */
#define NTI_MAX (NN / ITILE)    /* 16 */
#define NTJ_MAX (NN / JTILE)    /* 64 */
#define TA   128            /* attraction tasks: 4 batches x 32 chunks of 128 */
#define G2   740            /* K2 grid: 148 SMs x 5 blocks, single wave */
#define T2   128            /* K2 threads */

#define LOG2E  1.4426950408889634f
#define SCALE  1.6986436f   /* sqrt(2*log2(e)) */

typedef unsigned long long ull;

// ---------------- scratch (no allocations; zero-init valid) ----------------
__device__ float g_cp_emb[BB][NN][DD];   // compacted CP embeddings, pre-scaled by SCALE
__device__ float g_nsq   [BB][NN];       // -|e_raw|^2 * log2(e)
__device__ int   g_pos     [BB];
__device__ int   g_cnt     [BB][KK];
__device__ int   g_firstmax[BB][KK];     // max(NN - i); 0 = no CP
__device__ float g_bce1    [BB];
__device__ float g_bce0    [BB];
__device__ float g_seg     [BB][KK];
__device__ float g_repsum  [BB];
__device__ int   g_done;

__device__ __forceinline__ float ex2f(float x) {
    float r; asm("ex2.approx.ftz.f32 %0, %1;" : "=f"(r) : "f"(x)); return r;
}
__device__ __forceinline__ float softplus_f(float x) {
    return fmaxf(x, 0.f) + log1pf(expf(-fabsf(x)));
}
__device__ __forceinline__ ull ffma2(ull a, ull b, ull c) {
    ull d; asm("fma.rn.f32x2 %0, %1, %2, %3;" : "=l"(d) : "l"(a), "l"(b), "l"(c));
    return d;
}
__device__ __forceinline__ ull addx2(ull a, ull b) {
    ull d; asm("add.rn.f32x2 %0, %1, %2;" : "=l"(d) : "l"(a), "l"(b));
    return d;
}
__device__ __forceinline__ ull packx2(float lo, float hi) {
    ull d; asm("mov.b64 %0, {%1, %2};" : "=l"(d) : "f"(lo), "f"(hi));
    return d;
}
__device__ __forceinline__ void unpackx2(float& lo, float& hi, ull v) {
    asm("mov.b64 {%0, %1}, %2;" : "=f"(lo), "=f"(hi) : "l"(v));
}

// ============ kernel 1: counts, first-CP, BCE, scaled CP compaction ============
__global__ void __launch_bounds__(CH1) k_pass1(const float* __restrict__ beta,
                                               const float* __restrict__ embed,
                                               const int*   __restrict__ sid,
                                               const int*   __restrict__ iscp)
{
    const int c   = blockIdx.x;
    const int b   = blockIdx.y;
    const int tid = threadIdx.x;
    const int i   = c * CH1 + tid;
    const int g   = b * NN + i;
    const int lane = tid & 31;

    __shared__ int   s_cnt[KK];
    __shared__ int   s_first[KK];
    __shared__ float s_w1[CH1 / 32];
    __shared__ float s_w0[CH1 / 32];

    if (tid < KK) { s_cnt[tid] = 0; s_first[tid] = NN; }
    __syncthreads();

    const int   s  = sid[g];
    const int   cp = iscp[g];
    const float bt = beta[g];

    atomicAdd(&s_cnt[s], 1);
    float l1 = 0.f, l0 = 0.f;
    if (cp == 1) { atomicMin(&s_first[s], i); l1 = softplus_f(-bt); }
    else         { l0 = softplus_f(bt); }

    const unsigned bal = __ballot_sync(0xffffffffu, cp == 1);
    if (bal) {
        const int nw = __popc(bal);
        const int leader = __ffs(bal) - 1;
        int base = 0;
        if (lane == leader) base = atomicAdd(&g_pos[b], nw);
        base = __shfl_sync(0xffffffffu, base, leader);
        if (cp == 1) {
            const int w = base + __popc(bal & ((1u << lane) - 1u));
            const float4* e = (const float4*)&embed[(size_t)g * DD];
            float4 a = e[0], d = e[1];
            float sq = a.x*a.x + a.y*a.y + a.z*a.z + a.w*a.w
                     + d.x*d.x + d.y*d.y + d.z*d.z + d.w*d.w;
            *(float4*)&g_cp_emb[b][w][0] = make_float4(a.x*SCALE, a.y*SCALE, a.z*SCALE, a.w*SCALE);
            *(float4*)&g_cp_emb[b][w][4] = make_float4(d.x*SCALE, d.y*SCALE, d.z*SCALE, d.w*SCALE);
            g_nsq[b][w] = -sq * LOG2E;
        }
    }

    #pragma unroll
    for (int off = 16; off; off >>= 1) {
        l1 += __shfl_down_sync(0xffffffffu, l1, off);
        l0 += __shfl_down_sync(0xffffffffu, l0, off);
    }
    if (lane == 0) { s_w1[tid >> 5] = l1; s_w0[tid >> 5] = l0; }
    __syncthreads();

    if (tid < KK) {
        if (s_cnt[tid] > 0)    atomicAdd(&g_cnt[b][tid], s_cnt[tid]);
        if (s_first[tid] < NN) atomicMax(&g_firstmax[b][tid], NN - s_first[tid]);
    }
    if (tid == 0) {
        float S1 = 0.f, S0 = 0.f;
        #pragma unroll
        for (int w = 0; w < CH1 / 32; w++) { S1 += s_w1[w]; S0 += s_w0[w]; }
        atomicAdd(&g_bce1[b], S1);
        atomicAdd(&g_bce0[b], S0);
    }
}

// ============ kernel 2: task-queued attraction + repulsion + elected finalize ============
__global__ void __launch_bounds__(T2, 5) k_main(const float* __restrict__ embed,
                                                const int*   __restrict__ sid,
                                                float* __restrict__ out)
{
    const int t    = threadIdx.x;
    const int lane = t & 31;

    __shared__ __align__(16) ull sJ[JTILE/2 + 1][10];   // +1 pad row for prefetch
    __shared__ float sred[8];
    __shared__ float s_cpe[KK][DD];
    __shared__ int   s_f[KK];
    __shared__ float s_seg[KK];
    __shared__ int   s_P[BB];
    __shared__ int   s_last;

    if (t < BB) s_P[t] = g_pos[t];
    __syncthreads();

    // total task count (uniform)
    int total = TA;
    #pragma unroll
    for (int bb = 0; bb < BB; bb++) {
        int P   = s_P[bb];
        int nti = min(NTI_MAX, (P + ITILE - 1) >> 8);
        int ntj = min(NTJ_MAX, (P + JTILE - 1) >> 6);
        total += nti * ntj - (RATIO / 2) * nti * (nti - 1);  // sum_{ti<nti}(ntj - RATIO*ti)
    }

    for (int task = blockIdx.x; task < total; task += G2) {
        __syncthreads();                            // protect smem reuse across tasks
        if (task < TA) {
            // ---------------- attraction chunk ----------------
            const int b = task >> 5;
            const int c = task & 31;
            if (t < KK) {
                int m = g_firstmax[b][t];
                s_f[t]   = m;
                s_seg[t] = 0.f;
                if (m > 0) {
                    int f = NN - m;
                    const float4* e = (const float4*)&embed[((size_t)b * NN + f) * DD];
                    *(float4*)&s_cpe[t][0] = e[0];
                    *(float4*)&s_cpe[t][4] = e[1];
                }
            }
            __syncthreads();

            const int g = b * NN + c * T2 + t;
            const int s = sid[g];
            if (s_f[s] > 0) {
                const float4* e = (const float4*)&embed[(size_t)g * DD];
                float4 a = e[0], d = e[1];
                float x0 = a.x - s_cpe[s][0], x1 = a.y - s_cpe[s][1];
                float x2 = a.z - s_cpe[s][2], x3 = a.w - s_cpe[s][3];
                float x4 = d.x - s_cpe[s][4], x5 = d.y - s_cpe[s][5];
                float x6 = d.z - s_cpe[s][6], x7 = d.w - s_cpe[s][7];
                float d2 = x0*x0 + x1*x1 + x2*x2 + x3*x3 + x4*x4 + x5*x5 + x6*x6 + x7*x7;
                atomicAdd(&s_seg[s], d2);
            }
            __syncthreads();
            if (t < KK && s_seg[t] != 0.f) atomicAdd(&g_seg[b][t], s_seg[t]);
        } else {
            // ---------------- repulsion tile (256 i x 64 j) ----------------
            int q = task - TA;
            int b = 0, ntj = 0;
            #pragma unroll
            for (int bb = 0; bb < BB; bb++) {
                int P   = s_P[bb];
                int ti_ = min(NTI_MAX, (P + ITILE - 1) >> 8);
                int tj_ = min(NTJ_MAX, (P + JTILE - 1) >> 6);
                int tri = ti_ * tj_ - (RATIO / 2) * ti_ * (ti_ - 1);
                if (bb < BB - 1 && q >= tri) { q -= tri; b = bb + 1; }
                else if (bb == b) { ntj = tj_; }
            }
            int ti = 0, rem = ntj;
            while (q >= rem) { q -= rem; ti++; rem -= RATIO; }
            const int tj = RATIO * ti + q;

            const int P  = s_P[b];
            const int i0 = ti * ITILE;
            const int j0 = tj * JTILE;
            const int jn = min(JTILE, P - j0);

            // pack 32 j-pair rows into smem (from row-major global)
            if (t < JTILE / 2) {
                const int j0g = j0 + 2 * t;
                const int j1g = j0g + 1;
                float4 a0 = *(const float4*)&g_cp_emb[b][j0g][0];
                float4 a1 = *(const float4*)&g_cp_emb[b][j0g][4];
                float4 b0 = *(const float4*)&g_cp_emb[b][j1g][0];
                float4 b1 = *(const float4*)&g_cp_emb[b][j1g][4];
                float n0 = g_nsq[b][j0g], n1 = g_nsq[b][j1g];
                ull* row = sJ[t];
                row[0] = packx2(a0.x, b0.x); row[1] = packx2(a0.y, b0.y);
                row[2] = packx2(a0.z, b0.z); row[3] = packx2(a0.w, b0.w);
                row[4] = packx2(a1.x, b1.x); row[5] = packx2(a1.y, b1.y);
                row[6] = packx2(a1.z, b1.z); row[7] = packx2(a1.w, b1.w);
                row[8] = packx2(n0, n1);
            }

            // i-side: 2 rows per thread, broadcast-packed
            const int gi0 = i0 + t;
            const int gi1 = gi0 + 128;
            float4 ea0 = *(const float4*)&g_cp_emb[b][gi0][0];
            float4 eb0 = *(const float4*)&g_cp_emb[b][gi0][4];
            float4 ea1 = *(const float4*)&g_cp_emb[b][gi1][0];
            float4 eb1 = *(const float4*)&g_cp_emb[b][gi1][4];
            ull a0_0 = packx2(ea0.x, ea0.x), a0_1 = packx2(ea0.y, ea0.y);
            ull a0_2 = packx2(ea0.z, ea0.z), a0_3 = packx2(ea0.w, ea0.w);
            ull a0_4 = packx2(eb0.x, eb0.x), a0_5 = packx2(eb0.y, eb0.y);
            ull a0_6 = packx2(eb0.z, eb0.z), a0_7 = packx2(eb0.w, eb0.w);
            ull a1_0 = packx2(ea1.x, ea1.x), a1_1 = packx2(ea1.y, ea1.y);
            ull a1_2 = packx2(ea1.z, ea1.z), a1_3 = packx2(ea1.w, ea1.w);
            ull a1_4 = packx2(eb1.x, eb1.x), a1_5 = packx2(eb1.y, eb1.y);
            ull a1_6 = packx2(eb1.z, eb1.z), a1_7 = packx2(eb1.w, eb1.w);
            float nqs0 = (gi0 < P) ? g_nsq[b][gi0] : -3.0e38f;   // invalid -> ex2 underflow
            float nqs1 = (gi1 < P) ? g_nsq[b][gi1] : -3.0e38f;
            ull nq2_0 = packx2(nqs0, nqs0);
            ull nq2_1 = packx2(nqs1, nqs1);
            __syncthreads();

            float accA = 0.f, accB = 0.f, accC = 0.f, accD = 0.f;
            const bool clean = (tj >= RATIO * ti + RATIO) && (jn == JTILE);
            if (clean) {
                // software-pipelined: prefetch row jj+1 before the ex2/acc tail of jj
                ulonglong2 r01 = *(const ulonglong2*)&sJ[0][0];
                ulonglong2 r23 = *(const ulonglong2*)&sJ[0][2];
                ulonglong2 r45 = *(const ulonglong2*)&sJ[0][4];
                ulonglong2 r67 = *(const ulonglong2*)&sJ[0][6];
                ull seed = sJ[0][8];
                #pragma unroll 4
                for (int jj = 0; jj < JTILE / 2; jj++) {
                    // chains for current row
                    ull ca = ffma2(a0_0, r01.x, seed);
                    ca = ffma2(a0_1, r01.y, ca);
                    ca = ffma2(a0_2, r23.x, ca);
                    ca = ffma2(a0_3, r23.y, ca);
                    ull cb = ffma2(a0_4, r45.x, nq2_0);
                    cb = ffma2(a0_5, r45.y, cb);
                    cb = ffma2(a0_6, r67.x, cb);
                    cb = ffma2(a0_7, r67.y, cb);
                    ull da = ffma2(a1_0, r01.x, seed);
                    da = ffma2(a1_1, r01.y, da);
                    da = ffma2(a1_2, r23.x, da);
                    da = ffma2(a1_3, r23.y, da);
                    ull db = ffma2(a1_4, r45.x, nq2_1);
                    db = ffma2(a1_5, r45.y, db);
                    db = ffma2(a1_6, r67.x, db);
                    db = ffma2(a1_7, r67.y, db);
                    // prefetch next row (pad row makes jj+1 always safe)
                    const ull* nrow = sJ[jj + 1];
                    ulonglong2 p01 = *(const ulonglong2*)&nrow[0];
                    ulonglong2 p23 = *(const ulonglong2*)&nrow[2];
                    ulonglong2 p45 = *(const ulonglong2*)&nrow[4];
                    ulonglong2 p67 = *(const ulonglong2*)&nrow[6];
                    ull pseed = nrow[8];
                    // tail: combine, ex2, accumulate
                    float lo, hi;
                    unpackx2(lo, hi, addx2(ca, cb));
                    accA += ex2f(lo);
                    accB += ex2f(hi);
                    unpackx2(lo, hi, addx2(da, db));
                    accC += ex2f(lo);
                    accD += ex2f(hi);
                    // rotate buffers
                    r01 = p01; r23 = p23; r45 = p45; r67 = p67; seed = pseed;
                }
            } else {
                const int jn2 = (jn + 1) >> 1;
                for (int jj = 0; jj < jn2; jj++) {
                    const ull* row = sJ[jj];
                    ulonglong2 r01 = *(const ulonglong2*)&row[0];
                    ulonglong2 r23 = *(const ulonglong2*)&row[2];
                    ulonglong2 r45 = *(const ulonglong2*)&row[4];
                    ulonglong2 r67 = *(const ulonglong2*)&row[6];
                    ull seed = row[8];
                    const int jg0 = j0 + 2 * jj;
                    const int jg1 = jg0 + 1;
                    ull ca = ffma2(a0_0, r01.x, seed);
                    ca = ffma2(a0_1, r01.y, ca);
                    ca = ffma2(a0_2, r23.x, ca);
                    ca = ffma2(a0_3, r23.y, ca);
                    ull cb = ffma2(a0_4, r45.x, nq2_0);
                    cb = ffma2(a0_5, r45.y, cb);
                    cb = ffma2(a0_6, r67.x, cb);
                    cb = ffma2(a0_7, r67.y, cb);
                    float lo, hi;
                    unpackx2(lo, hi, addx2(ca, cb));
                    accA += (jg0 > gi0 && jg0 < P) ? ex2f(lo) : 0.f;
                    accB += (jg1 > gi0 && jg1 < P) ? ex2f(hi) : 0.f;
                    ull da = ffma2(a1_0, r01.x, seed);
                    da = ffma2(a1_1, r01.y, da);
                    da = ffma2(a1_2, r23.x, da);
                    da = ffma2(a1_3, r23.y, da);
                    ull db = ffma2(a1_4, r45.x, nq2_1);
                    db = ffma2(a1_5, r45.y, db);
                    db = ffma2(a1_6, r67.x, db);
                    db = ffma2(a1_7, r67.y, db);
                    unpackx2(lo, hi, addx2(da, db));
                    accC += (jg0 > gi1 && jg0 < P) ? ex2f(lo) : 0.f;
                    accD += (jg1 > gi1 && jg1 < P) ? ex2f(hi) : 0.f;
                }
            }

            float acc = (accA + accB) + (accC + accD);
            #pragma unroll
            for (int off = 16; off; off >>= 1)
                acc += __shfl_down_sync(0xffffffffu, acc, off);
            if (lane == 0) atomicAdd(&g_repsum[b], acc);
        }
    }

    // ---------------- global election ----------------
    __threadfence();
    __syncthreads();
    if (t == 0) {
        int old = atomicAdd(&g_done, 1);
        s_last = (old == G2 - 1);
    }
    __syncthreads();
    if (!s_last) return;
    __threadfence();

    // ======== finalize (one block; warp w handles batch w) ========
    {
        const int b = t >> 5;
        float attr = 0.f;
        #pragma unroll
        for (int qq = 0; qq < KK / 32; qq++) {
            int k = lane + qq * 32;
            int m   = g_firstmax[b][k];
            int cnt = g_cnt[b][k];
            float seg = g_seg[b][k];
            attr += (m > 0 && cnt > 0) ? seg / fmaxf((float)cnt, 1.f) : 0.f;
        }
        #pragma unroll
        for (int off = 16; off; off >>= 1)
            attr += __shfl_down_sync(0xffffffffu, attr, off);
        if (lane == 0) {
            float pos = (float)s_P[b];
            float neg = (float)NN - pos;
            int   valid = (pos >= 1.f) && (neg >= 1.f);
            float pw  = neg / (pos + 1e-6f);
            float bce = (pw * g_bce1[b] + g_bce0[b]) / (float)NN;
            float S   = g_repsum[b];
            float rep_sum = pos + 2.f * S;                 // diagonal = pos exactly
            float rep = (pos > 1.f) ? rep_sum / fmaxf(pos * pos, 1.f) : 0.f;
            sred[b]     = valid ? (bce + attr + rep) : 0.f;
            sred[4 + b] = valid ? 1.f : 0.f;
        }
    }
    __syncthreads();
    if (t == 0) {
        float ts = 0.f, cnt = 0.f;
        #pragma unroll
        for (int bb = 0; bb < BB; bb++) { ts += sred[bb]; cnt += sred[4 + bb]; }
        out[0] = (cnt > 0.f) ? ts / fmaxf(cnt, 1.f) : 0.f;
    }
    __syncthreads();
    // reset accumulators for the next graph replay
    for (int idx = t; idx < BB * KK; idx += T2) {
        int bb = idx >> 6, k = idx & 63;
        g_cnt[bb][k]      = 0;
        g_firstmax[bb][k] = 0;
        g_seg[bb][k]      = 0.f;
    }
    if (t < BB) {
        g_pos[t]    = 0;
        g_repsum[t] = 0.f;
        g_bce1[t]   = 0.f;
        g_bce0[t]   = 0.f;
    }
    if (t == 0) g_done = 0;
}

// ================= launch =================
extern "C" void kernel_launch(void* const* d_in, const int* in_sizes, int n_in,
                              void* d_out, int out_size)
{
    const float* beta  = (const float*)d_in[0];
    const float* embed = (const float*)d_in[1];
    const int*   sid   = (const int*)  d_in[2];
    const int*   iscp  = (const int*)  d_in[3];
    float* out = (float*)d_out;

    dim3 g1(CC1, BB);
    k_pass1<<<g1, CH1>>>(beta, embed, sid, iscp);
    k_main<<<G2, T2>>>(embed, sid, out);
}